// round 1
// baseline (speedup 1.0000x reference)
#include <cuda_runtime.h>
#include <cstdint>

#define NN 100000
#define EE 1600000
#define HID 64
#define NH 4
#define DHD 16
#define OC 32
#define EPSV 1e-5f

// ---------------- scratch (device globals; no allocation allowed) ----------------
__device__ float    g_q[(size_t)NN * HID];
__device__ float    g_k[(size_t)NN * HID];
__device__ float    g_v[(size_t)NN * HID];
__device__ float    g_skip[(size_t)NN * HID];
__device__ float    g_alpha[(size_t)EE * NH];
__device__ unsigned g_amax[(size_t)NN * NH];
__device__ float    g_denom[(size_t)NN * NH];
__device__ float    g_acc[(size_t)NN * HID];
__device__ float    g_x[(size_t)NN * HID];

// ordered-uint encoding of float for atomicMax (monotonic for all finite floats)
__device__ __forceinline__ unsigned fenc(float f) {
    unsigned u = __float_as_uint(f);
    return (u & 0x80000000u) ? ~u : (u | 0x80000000u);
}
__device__ __forceinline__ float fdec(unsigned u) {
    return (u & 0x80000000u) ? __uint_as_float(u ^ 0x80000000u) : __uint_as_float(~u);
}

__device__ __forceinline__ void red_add_v4(float* p, float a, float b, float c, float d) {
    asm volatile("red.global.add.v4.f32 [%0], {%1,%2,%3,%4};"
                 :: "l"(p), "f"(a), "f"(b), "f"(c), "f"(d) : "memory");
}

// ---------------- fused QKVS GEMM: [16 rows/block] x [256 out cols] ----------------
// 256 threads: thread t computes column (t&63) of matrix sel=(t>>6) for 16 rows.
__global__ void k_gemm_qkvs(const float* __restrict__ xin,   // null => read g_x
                            const float* __restrict__ Wq, const float* __restrict__ Wk,
                            const float* __restrict__ Wv, const float* __restrict__ Ws,
                            const float* __restrict__ bq, const float* __restrict__ bk,
                            const float* __restrict__ bv, const float* __restrict__ bs) {
    __shared__ float xs[16 * 64];
    const float* x = xin ? xin : g_x;
    int t = threadIdx.x;
    int row0 = blockIdx.x * 16;
    // load 16 rows x 64 cols = 1024 floats = 256 float4
    ((float4*)xs)[t] = ((const float4*)(x + (size_t)row0 * 64))[t];
    __syncthreads();

    int sel = t >> 6, cc = t & 63;
    const float* W; const float* bias; float* outp;
    if (sel == 0)      { W = Wq; bias = bq; outp = g_q; }
    else if (sel == 1) { W = Wk; bias = bk; outp = g_k; }
    else if (sel == 2) { W = Wv; bias = bv; outp = g_v; }
    else               { W = Ws; bias = bs; outp = g_skip; }

    float acc[16];
    float bb = bias[cc];
#pragma unroll
    for (int r = 0; r < 16; r++) acc[r] = bb;

#pragma unroll 4
    for (int kk = 0; kk < 64; kk++) {
        float w = W[kk * 64 + cc];
#pragma unroll
        for (int r = 0; r < 16; r++) acc[r] = fmaf(xs[r * 64 + kk], w, acc[r]);
    }
#pragma unroll
    for (int r = 0; r < 16; r++) outp[(size_t)(row0 + r) * 64 + cc] = acc[r];
}

// ---------------- zero accumulators ----------------
__global__ void k_init() {
    int idx = blockIdx.x * blockDim.x + threadIdx.x;
    if (idx < NN * HID) g_acc[idx] = 0.f;
    if (idx < NN * NH) { g_amax[idx] = 0u; g_denom[idx] = 0.f; }
}

// ---------------- edge pass 1: alpha + segment max ----------------
__global__ void k_edge1(const int* __restrict__ ei) {
    int idx = blockIdx.x * blockDim.x + threadIdx.x;
    if (idx >= EE * NH) return;
    int e = idx >> 2, h = idx & 3;
    int s = ei[e], d = ei[EE + e];
    const float4* qp = (const float4*)(g_q + (size_t)d * 64 + h * 16);
    const float4* kp = (const float4*)(g_k + (size_t)s * 64 + h * 16);
    float dot = 0.f;
#pragma unroll
    for (int i = 0; i < 4; i++) {
        float4 a = qp[i], b = kp[i];
        dot += a.x * b.x + a.y * b.y + a.z * b.z + a.w * b.w;
    }
    float alpha = dot * 0.25f;   // 1/sqrt(16)
    g_alpha[idx] = alpha;
    atomicMax(&g_amax[d * 4 + h], fenc(alpha));
}

// ---------------- edge pass 2: exp, denom, weighted-v scatter ----------------
__global__ void k_edge2(const int* __restrict__ ei) {
    int idx = blockIdx.x * blockDim.x + threadIdx.x;
    if (idx >= EE * NH) return;
    int e = idx >> 2, h = idx & 3;
    int s = ei[e], d = ei[EE + e];
    float m = fdec(g_amax[d * 4 + h]);
    float ex = expf(g_alpha[idx] - m);
    atomicAdd(&g_denom[d * 4 + h], ex);
    const float4* vp = (const float4*)(g_v + (size_t)s * 64 + h * 16);
    float* op = g_acc + (size_t)d * 64 + h * 16;
#pragma unroll
    for (int i = 0; i < 4; i++) {
        float4 vv = vp[i];
        red_add_v4(op + i * 4, ex * vv.x, ex * vv.y, ex * vv.z, ex * vv.w);
    }
}

// ---------------- node epilogue: normalize + skip + BN + ReLU ----------------
__global__ void k_node(const float* __restrict__ bg, const float* __restrict__ bb,
                       const float* __restrict__ bm, const float* __restrict__ bv) {
    int idx = blockIdx.x * blockDim.x + threadIdx.x;
    if (idx >= NN * HID) return;
    int c = idx & 63, h = c >> 4;
    int node = idx >> 6;
    float den = g_denom[node * 4 + h];
    float val = (den > 0.f) ? g_acc[idx] / den : 0.f;
    val += g_skip[idx];
    val = (val - bm[c]) * rsqrtf(bv[c] + EPSV) * bg[c] + bb[c];
    g_x[idx] = fmaxf(val, 0.f);
}

// ---------------- head GEMM: [N,64] x [64,32] ----------------
__global__ void k_head(const float* __restrict__ Wh, const float* __restrict__ bh,
                       float* __restrict__ out) {
    __shared__ float xs[8 * 64];
    __shared__ float ws[64 * 32];
    int t = threadIdx.x;
    int node0 = blockIdx.x * 8;
    xs[t]       = g_x[(size_t)node0 * 64 + t];
    xs[t + 256] = g_x[(size_t)node0 * 64 + t + 256];
#pragma unroll
    for (int i = 0; i < 8; i++) ws[t + 256 * i] = Wh[t + 256 * i];
    __syncthreads();
    int ln = t >> 5, col = t & 31;
    float acc = bh[col];
#pragma unroll 4
    for (int kk = 0; kk < 64; kk++)
        acc = fmaf(xs[ln * 64 + kk], ws[kk * 32 + col], acc);
    out[(size_t)(node0 + ln) * 32 + col] = acc;
}

// ---------------- launch ----------------
extern "C" void kernel_launch(void* const* d_in, const int* in_sizes, int n_in,
                              void* d_out, int out_size) {
    const float* x    = (const float*)d_in[0];
    const int*   ei   = (const int*)  d_in[1];
    const float* Wq   = (const float*)d_in[2];
    const float* bq   = (const float*)d_in[3];
    const float* Wk   = (const float*)d_in[4];
    const float* bk   = (const float*)d_in[5];
    const float* Wv   = (const float*)d_in[6];
    const float* bv   = (const float*)d_in[7];
    const float* Ws   = (const float*)d_in[8];
    const float* bs   = (const float*)d_in[9];
    const float* bn_g = (const float*)d_in[10];
    const float* bn_b = (const float*)d_in[11];
    const float* bn_m = (const float*)d_in[12];
    const float* bn_v = (const float*)d_in[13];
    const float* Wh   = (const float*)d_in[14];
    const float* bh   = (const float*)d_in[15];
    float* out = (float*)d_out;

    const int GE = (EE * NH) / 256;        // 25000
    const int GN = (NN * HID) / 256;       // 25000
    const int GG = NN / 16;                // 6250
    const int GH = NN / 8;                 // 12500

    for (int l = 0; l < 3; l++) {
        size_t wo = (size_t)l * HID * HID;
        size_t bo = (size_t)l * HID;
        const float* xin = (l == 0) ? x : nullptr;
        k_gemm_qkvs<<<GG, 256>>>(xin, Wq + wo, Wk + wo, Wv + wo, Ws + wo,
                                 bq + bo, bk + bo, bv + bo, bs + bo);
        k_init<<<GN, 256>>>();
        k_edge1<<<GE, 256>>>(ei);
        k_edge2<<<GE, 256>>>(ei);
        k_node<<<GN, 256>>>(bn_g + bo, bn_b + bo, bn_m + bo, bn_v + bo);
    }
    k_head<<<GH, 256>>>(Wh, bh, out);
}

// round 2
// speedup vs baseline: 1.7165x; 1.7165x over previous
#include <cuda_runtime.h>
#include <cstdint>

#define NN 100000
#define EE 1600000
#define HID 64
#define NH 4
#define OC 32
#define EPSV 1e-5f

// ---------------- scratch (device globals) ----------------
__device__ float g_q[(size_t)NN * HID];
__device__ float g_k[(size_t)NN * HID];
__device__ float g_v[(size_t)NN * HID];
__device__ float g_skip[(size_t)NN * HID];
__device__ float g_x[(size_t)NN * HID];

__device__ int g_cnt[NN];
__device__ int g_rowstart[NN + 1];
__device__ int g_cursor[NN];
__device__ int g_csrsrc[EE];
__device__ int g_bsum[128];
__device__ int g_boff[128];

// ================= CSR build (once per launch, reused by 3 layers) =================
__global__ void k_zero_cnt() {
    int i = blockIdx.x * blockDim.x + threadIdx.x;
    if (i < NN) g_cnt[i] = 0;
}

__global__ void k_hist(const int* __restrict__ ei) {
    int e = blockIdx.x * blockDim.x + threadIdx.x;
    if (e < EE) atomicAdd(&g_cnt[ei[EE + e]], 1);
}

// block-level Hillis-Steele scan, 1024 elems per block
__global__ void k_scan1() {
    __shared__ int sh[1024];
    int i = blockIdx.x * 1024 + threadIdx.x;
    int v = (i < NN) ? g_cnt[i] : 0;
    sh[threadIdx.x] = v;
    __syncthreads();
    for (int off = 1; off < 1024; off <<= 1) {
        int t = (threadIdx.x >= off) ? sh[threadIdx.x - off] : 0;
        __syncthreads();
        sh[threadIdx.x] += t;
        __syncthreads();
    }
    if (i < NN) g_rowstart[i] = sh[threadIdx.x] - v;   // exclusive
    if (threadIdx.x == 1023) g_bsum[blockIdx.x] = sh[1023];
}

__global__ void k_scan2(int nblk) {
    if (threadIdx.x == 0) {
        int run = 0;
        for (int b = 0; b < nblk; b++) { g_boff[b] = run; run += g_bsum[b]; }
    }
}

__global__ void k_scan3() {
    int i = blockIdx.x * blockDim.x + threadIdx.x;
    if (i < NN) {
        int rs = g_rowstart[i] + g_boff[i >> 10];
        g_rowstart[i] = rs;
        g_cursor[i] = rs;
    }
    if (i == 0) g_rowstart[NN] = EE;
}

__global__ void k_scatter(const int* __restrict__ ei) {
    int e = blockIdx.x * blockDim.x + threadIdx.x;
    if (e >= EE) return;
    int s = ei[e], d = ei[EE + e];
    int pos = atomicAdd(&g_cursor[d], 1);
    g_csrsrc[pos] = s;
}

// ================= fused QKVS GEMM (unchanged from R1) =================
__global__ void k_gemm_qkvs(const float* __restrict__ xin,
                            const float* __restrict__ Wq, const float* __restrict__ Wk,
                            const float* __restrict__ Wv, const float* __restrict__ Ws,
                            const float* __restrict__ bq, const float* __restrict__ bk,
                            const float* __restrict__ bv, const float* __restrict__ bs) {
    __shared__ float xs[16 * 64];
    const float* x = xin ? xin : g_x;
    int t = threadIdx.x;
    int row0 = blockIdx.x * 16;
    ((float4*)xs)[t] = ((const float4*)(x + (size_t)row0 * 64))[t];
    __syncthreads();

    int sel = t >> 6, cc = t & 63;
    const float* W; const float* bias; float* outp;
    if (sel == 0)      { W = Wq; bias = bq; outp = g_q; }
    else if (sel == 1) { W = Wk; bias = bk; outp = g_k; }
    else if (sel == 2) { W = Wv; bias = bv; outp = g_v; }
    else               { W = Ws; bias = bs; outp = g_skip; }

    float acc[16];
    float bb = bias[cc];
#pragma unroll
    for (int r = 0; r < 16; r++) acc[r] = bb;
#pragma unroll 4
    for (int kk = 0; kk < 64; kk++) {
        float w = W[kk * 64 + cc];
#pragma unroll
        for (int r = 0; r < 16; r++) acc[r] = fmaf(xs[r * 64 + kk], w, acc[r]);
    }
#pragma unroll
    for (int r = 0; r < 16; r++) outp[(size_t)(row0 + r) * 64 + cc] = acc[r];
}

// ================= fused attention: warp per dst node, gather over CSR =================
// Lane l owns channels (2l, 2l+1). Lanes [8h, 8h+8) form head h's group (channels 16h..16h+15).
// Per edge: per-head dot via 3 shfl.xor, exp, accumulate ex*v and denom in registers.
// Epilogue: normalize + skip + BN + ReLU, all in-register. NO atomics, NO max pass
// (alpha is O(1) here, exp is safe; softmax is shift-invariant).
__global__ void k_attn(const float* __restrict__ bg, const float* __restrict__ bb,
                       const float* __restrict__ bm, const float* __restrict__ bvv) {
    int warp = (blockIdx.x * blockDim.x + threadIdx.x) >> 5;
    int lane = threadIdx.x & 31;
    if (warp >= NN) return;
    int node = warp;

    const float2* q2 = (const float2*)(g_q + (size_t)node * 64);
    float2 qv = q2[lane];

    int beg = g_rowstart[node];
    int end = g_rowstart[node + 1];

    float2 acc = make_float2(0.f, 0.f);
    float den = 0.f;

    for (int i = beg; i < end; i++) {
        int s = g_csrsrc[i];
        const float2* k2 = (const float2*)(g_k + (size_t)s * 64);
        const float2* v2 = (const float2*)(g_v + (size_t)s * 64);
        float2 kv = k2[lane];
        float part = qv.x * kv.x + qv.y * kv.y;
        // reduce within 8-lane head group
        part += __shfl_xor_sync(0xffffffffu, part, 1);
        part += __shfl_xor_sync(0xffffffffu, part, 2);
        part += __shfl_xor_sync(0xffffffffu, part, 4);
        float ex = __expf(part * 0.25f);   // 1/sqrt(16)
        float2 vv = v2[lane];
        acc.x = fmaf(ex, vv.x, acc.x);
        acc.y = fmaf(ex, vv.y, acc.y);
        den += ex;
    }

    float inv = (den > 0.f) ? __frcp_rn(den) : 0.f;
    int c0 = lane * 2, c1 = c0 + 1;
    const float2* sk2 = (const float2*)(g_skip + (size_t)node * 64);
    float2 sk = sk2[lane];
    float v0 = acc.x * inv + sk.x;
    float v1 = acc.y * inv + sk.y;
    v0 = (v0 - bm[c0]) * rsqrtf(bvv[c0] + EPSV) * bg[c0] + bb[c0];
    v1 = (v1 - bm[c1]) * rsqrtf(bvv[c1] + EPSV) * bg[c1] + bb[c1];
    float2 r = make_float2(fmaxf(v0, 0.f), fmaxf(v1, 0.f));
    ((float2*)(g_x + (size_t)node * 64))[lane] = r;
}

// ================= head GEMM: [N,64] x [64,32] =================
__global__ void k_head(const float* __restrict__ Wh, const float* __restrict__ bh,
                       float* __restrict__ out) {
    __shared__ float xs[8 * 64];
    __shared__ float ws[64 * 32];
    int t = threadIdx.x;
    int node0 = blockIdx.x * 8;
    xs[t]       = g_x[(size_t)node0 * 64 + t];
    xs[t + 256] = g_x[(size_t)node0 * 64 + t + 256];
#pragma unroll
    for (int i = 0; i < 8; i++) ws[t + 256 * i] = Wh[t + 256 * i];
    __syncthreads();
    int ln = t >> 5, col = t & 31;
    float acc = bh[col];
#pragma unroll 4
    for (int kk = 0; kk < 64; kk++)
        acc = fmaf(xs[ln * 64 + kk], ws[kk * 32 + col], acc);
    out[(size_t)(node0 + ln) * 32 + col] = acc;
}

// ================= launch =================
extern "C" void kernel_launch(void* const* d_in, const int* in_sizes, int n_in,
                              void* d_out, int out_size) {
    const float* x    = (const float*)d_in[0];
    const int*   ei   = (const int*)  d_in[1];
    const float* Wq   = (const float*)d_in[2];
    const float* bq   = (const float*)d_in[3];
    const float* Wk   = (const float*)d_in[4];
    const float* bk   = (const float*)d_in[5];
    const float* Wv   = (const float*)d_in[6];
    const float* bv   = (const float*)d_in[7];
    const float* Ws   = (const float*)d_in[8];
    const float* bs   = (const float*)d_in[9];
    const float* bn_g = (const float*)d_in[10];
    const float* bn_b = (const float*)d_in[11];
    const float* bn_m = (const float*)d_in[12];
    const float* bn_v = (const float*)d_in[13];
    const float* Wh   = (const float*)d_in[14];
    const float* bh   = (const float*)d_in[15];
    float* out = (float*)d_out;

    const int NB   = (NN + 255) / 256;
    const int EB   = (EE + 255) / 256;
    const int SBLK = (NN + 1023) / 1024;   // 98
    const int GG   = NN / 16;              // 6250
    const int GA   = (NN * 32 + 255) / 256;// warp per node, 8 warps/block
    const int GH   = NN / 8;

    // CSR build (dst -> list of src), once; reused by all 3 layers
    k_zero_cnt<<<NB, 256>>>();
    k_hist<<<EB, 256>>>(ei);
    k_scan1<<<SBLK, 1024>>>();
    k_scan2<<<1, 32>>>(SBLK);
    k_scan3<<<NB, 256>>>();
    k_scatter<<<EB, 256>>>(ei);

    for (int l = 0; l < 3; l++) {
        size_t wo = (size_t)l * HID * HID;
        size_t bo = (size_t)l * HID;
        const float* xin = (l == 0) ? x : nullptr;
        k_gemm_qkvs<<<GG, 256>>>(xin, Wq + wo, Wk + wo, Wv + wo, Ws + wo,
                                 bq + bo, bk + bo, bv + bo, bs + bo);
        k_attn<<<GA, 256>>>(bn_g + bo, bn_b + bo, bn_m + bo, bn_v + bo);
    }
    k_head<<<GH, 256>>>(Wh, bh, out);
}

// round 3
// speedup vs baseline: 2.2698x; 1.3223x over previous
#include <cuda_runtime.h>
#include <cuda_fp16.h>
#include <cstdint>

#define NN 100000
#define EE 1600000
#define HID 64
#define OC 32
#define EPSV 1e-5f

// ---------------- scratch (device globals) ----------------
__device__ float  g_q[(size_t)NN * HID];
__device__ float  g_skip[(size_t)NN * HID];
__device__ float  g_x[(size_t)NN * HID];
__device__ __half g_kvh[(size_t)NN * 128];      // per node: k[64] halves, then v[64] halves
__device__ float4 g_wf[4 * 8 * 8 * 32];         // W in mma B-frag order: {bhi0,bhi1,blo0,blo1}

__device__ int g_cnt[NN];
__device__ int g_rowstart[NN + 1];
__device__ int g_cursor[NN];
__device__ int g_csrsrc[EE];
__device__ int g_bsum[128];
__device__ int g_boff[128];

// ================= CSR build (once, reused by 3 layers) =================
__global__ void k_zero_cnt() {
    int i = blockIdx.x * blockDim.x + threadIdx.x;
    if (i < NN) g_cnt[i] = 0;
}
__global__ void k_hist(const int* __restrict__ ei) {
    int e = blockIdx.x * blockDim.x + threadIdx.x;
    if (e < EE) atomicAdd(&g_cnt[ei[EE + e]], 1);
}
__global__ void k_scan1() {
    __shared__ int sh[1024];
    int i = blockIdx.x * 1024 + threadIdx.x;
    int v = (i < NN) ? g_cnt[i] : 0;
    sh[threadIdx.x] = v;
    __syncthreads();
    for (int off = 1; off < 1024; off <<= 1) {
        int t = (threadIdx.x >= off) ? sh[threadIdx.x - off] : 0;
        __syncthreads();
        sh[threadIdx.x] += t;
        __syncthreads();
    }
    if (i < NN) g_rowstart[i] = sh[threadIdx.x] - v;
    if (threadIdx.x == 1023) g_bsum[blockIdx.x] = sh[1023];
}
__global__ void k_scan2(int nblk) {        // parallel 128-wide scan (was serial: 8us)
    __shared__ int sh[128];
    int t = threadIdx.x;
    int v = (t < nblk) ? g_bsum[t] : 0;
    sh[t] = v;
    __syncthreads();
    for (int off = 1; off < 128; off <<= 1) {
        int u = (t >= off) ? sh[t - off] : 0;
        __syncthreads();
        sh[t] += u;
        __syncthreads();
    }
    if (t < nblk) g_boff[t] = sh[t] - v;
}
__global__ void k_scan3() {
    int i = blockIdx.x * blockDim.x + threadIdx.x;
    if (i < NN) {
        int rs = g_rowstart[i] + g_boff[i >> 10];
        g_rowstart[i] = rs;
        g_cursor[i] = rs;
    }
    if (i == 0) g_rowstart[NN] = EE;
}
__global__ void k_scatter(const int* __restrict__ ei) {
    int e = blockIdx.x * blockDim.x + threadIdx.x;
    if (e >= EE) return;
    int s = ei[e], d = ei[EE + e];
    int pos = atomicAdd(&g_cursor[d], 1);
    g_csrsrc[pos] = s;
}

// ================= W fragment prep (per layer): tf32 hi/lo in B-frag order =================
__device__ __forceinline__ uint32_t f2tf32(float f) {
    uint32_t u;
    asm("cvt.rna.tf32.f32 %0, %1;" : "=r"(u) : "f"(f));
    return u;
}
__global__ void k_wprep(const float* __restrict__ Wq, const float* __restrict__ Wk,
                        const float* __restrict__ Wv, const float* __restrict__ Ws) {
    int t = blockIdx.x * blockDim.x + threadIdx.x;   // 4*8*8*32 = 8192
    if (t >= 8192) return;
    int lane = t & 31;
    int nt   = (t >> 5) & 7;
    int kt   = (t >> 8) & 7;
    int sel  = t >> 11;
    const float* W = (sel == 0) ? Wq : (sel == 1) ? Wk : (sel == 2) ? Wv : Ws;
    int k0 = kt * 8 + (lane & 3);
    int n  = nt * 8 + (lane >> 2);
    float b0 = W[k0 * 64 + n];
    float b1 = W[(k0 + 4) * 64 + n];
    float h0 = __uint_as_float(f2tf32(b0));
    float h1 = __uint_as_float(f2tf32(b1));
    float l0 = __uint_as_float(f2tf32(b0 - h0));
    float l1 = __uint_as_float(f2tf32(b1 - h1));
    g_wf[t] = make_float4(h0, h1, l0, l1);
}

// ================= tensor-core QKVS GEMM (3xTF32, fp32-accurate) =================
__device__ __forceinline__ void mma_tf32(float c[4], uint32_t a0, uint32_t a1,
                                         uint32_t a2, uint32_t a3,
                                         uint32_t b0, uint32_t b1) {
    asm volatile("mma.sync.aligned.m16n8k8.row.col.f32.tf32.tf32.f32 "
                 "{%0,%1,%2,%3}, {%4,%5,%6,%7}, {%8,%9}, {%0,%1,%2,%3};"
                 : "+f"(c[0]), "+f"(c[1]), "+f"(c[2]), "+f"(c[3])
                 : "r"(a0), "r"(a1), "r"(a2), "r"(a3), "r"(b0), "r"(b1));
}

// grid (ceil(N/128), 4); block 256. Warp w -> 128 rows x 8 cols of matrix blockIdx.y.
__global__ void __launch_bounds__(256) k_gemm_mma(
        const float* __restrict__ xin,
        const float* __restrict__ bq, const float* __restrict__ bk,
        const float* __restrict__ bv, const float* __restrict__ bs) {
    __shared__ float xs[128 * 68];   // pad 68: conflict-free frag loads
    const float* x = xin ? xin : g_x;
    int row0 = blockIdx.x * 128;
    int t = threadIdx.x;

#pragma unroll
    for (int i = 0; i < 8; i++) {
        int idx = t + 256 * i;          // 2048 float4s: 16 per row
        int r = idx >> 4, c4 = idx & 15;
        float4 val = make_float4(0.f, 0.f, 0.f, 0.f);
        if (row0 + r < NN) val = ((const float4*)(x + (size_t)(row0 + r) * 64))[c4];
        *(float4*)(&xs[r * 68 + c4 * 4]) = val;
    }
    __syncthreads();

    int sel = blockIdx.y;
    int wid = t >> 5, lane = t & 31;
    int tig = lane & 3, grp = lane >> 2;
    int cloc = wid * 8 + 2 * tig;
    const float* bias = (sel == 0) ? bq : (sel == 1) ? bk : (sel == 2) ? bv : bs;
    float bias0 = bias[cloc], bias1 = bias[cloc + 1];

    float acc[8][4];
#pragma unroll
    for (int mt = 0; mt < 8; mt++) {
        acc[mt][0] = bias0; acc[mt][1] = bias1;
        acc[mt][2] = bias0; acc[mt][3] = bias1;
    }

#pragma unroll
    for (int kt = 0; kt < 8; kt++) {
        float4 bf = g_wf[((sel * 8 + kt) * 8 + wid) * 32 + lane];
        uint32_t bh0 = __float_as_uint(bf.x), bh1 = __float_as_uint(bf.y);
        uint32_t bl0 = __float_as_uint(bf.z), bl1 = __float_as_uint(bf.w);
        int k = kt * 8 + tig;
#pragma unroll
        for (int mt = 0; mt < 8; mt++) {
            int r = mt * 16 + grp;
            float a0 = xs[r * 68 + k];
            float a1 = xs[(r + 8) * 68 + k];
            float a2 = xs[r * 68 + k + 4];
            float a3 = xs[(r + 8) * 68 + k + 4];
            uint32_t h0 = f2tf32(a0), h1 = f2tf32(a1), h2 = f2tf32(a2), h3 = f2tf32(a3);
            uint32_t l0 = f2tf32(a0 - __uint_as_float(h0));
            uint32_t l1 = f2tf32(a1 - __uint_as_float(h1));
            uint32_t l2 = f2tf32(a2 - __uint_as_float(h2));
            uint32_t l3 = f2tf32(a3 - __uint_as_float(h3));
            mma_tf32(acc[mt], h0, h1, h2, h3, bh0, bh1);
            mma_tf32(acc[mt], h0, h1, h2, h3, bl0, bl1);
            mma_tf32(acc[mt], l0, l1, l2, l3, bh0, bh1);
        }
    }

#pragma unroll
    for (int mt = 0; mt < 8; mt++) {
        int r0g = row0 + mt * 16 + grp;
        int r1g = r0g + 8;
        if (sel == 0) {
            if (r0g < NN) *(float2*)(g_q + (size_t)r0g * 64 + cloc) = make_float2(acc[mt][0], acc[mt][1]);
            if (r1g < NN) *(float2*)(g_q + (size_t)r1g * 64 + cloc) = make_float2(acc[mt][2], acc[mt][3]);
        } else if (sel == 3) {
            if (r0g < NN) *(float2*)(g_skip + (size_t)r0g * 64 + cloc) = make_float2(acc[mt][0], acc[mt][1]);
            if (r1g < NN) *(float2*)(g_skip + (size_t)r1g * 64 + cloc) = make_float2(acc[mt][2], acc[mt][3]);
        } else {
            int off = (sel == 2) ? 64 : 0;
            if (r0g < NN) *(__half2*)(g_kvh + (size_t)r0g * 128 + off + cloc) =
                __floats2half2_rn(acc[mt][0], acc[mt][1]);
            if (r1g < NN) *(__half2*)(g_kvh + (size_t)r1g * 128 + off + cloc) =
                __floats2half2_rn(acc[mt][2], acc[mt][3]);
        }
    }
}

// ================= fused attention: warp/node, fp16 kv gather, batch-4 =================
__global__ void k_attn(const float* __restrict__ bg, const float* __restrict__ bb,
                       const float* __restrict__ bm, const float* __restrict__ bvv) {
    int warp = (blockIdx.x * blockDim.x + threadIdx.x) >> 5;
    int lane = threadIdx.x & 31;
    if (warp >= NN) return;
    int node = warp;

    float2 qv = ((const float2*)(g_q + (size_t)node * 64))[lane];
    int beg = g_rowstart[node];
    int end = g_rowstart[node + 1];

    float2 acc = make_float2(0.f, 0.f);
    float den = 0.f;
    int i = beg;

    for (; i + 4 <= end; i += 4) {
        int s0 = g_csrsrc[i], s1 = g_csrsrc[i + 1], s2 = g_csrsrc[i + 2], s3 = g_csrsrc[i + 3];
        const __half2* r0 = (const __half2*)(g_kvh + (size_t)s0 * 128);
        const __half2* r1 = (const __half2*)(g_kvh + (size_t)s1 * 128);
        const __half2* r2 = (const __half2*)(g_kvh + (size_t)s2 * 128);
        const __half2* r3 = (const __half2*)(g_kvh + (size_t)s3 * 128);
        __half2 ka = r0[lane], kb = r1[lane], kc = r2[lane], kd = r3[lane];
        __half2 va = r0[32 + lane], vb = r1[32 + lane], vc = r2[32 + lane], vd = r3[32 + lane];

        float2 f0 = __half22float2(ka), f1 = __half22float2(kb);
        float2 f2 = __half22float2(kc), f3 = __half22float2(kd);
        float p0 = fmaf(qv.x, f0.x, qv.y * f0.y);
        float p1 = fmaf(qv.x, f1.x, qv.y * f1.y);
        float p2 = fmaf(qv.x, f2.x, qv.y * f2.y);
        float p3 = fmaf(qv.x, f3.x, qv.y * f3.y);
        p0 += __shfl_xor_sync(0xffffffffu, p0, 1);
        p1 += __shfl_xor_sync(0xffffffffu, p1, 1);
        p2 += __shfl_xor_sync(0xffffffffu, p2, 1);
        p3 += __shfl_xor_sync(0xffffffffu, p3, 1);
        p0 += __shfl_xor_sync(0xffffffffu, p0, 2);
        p1 += __shfl_xor_sync(0xffffffffu, p1, 2);
        p2 += __shfl_xor_sync(0xffffffffu, p2, 2);
        p3 += __shfl_xor_sync(0xffffffffu, p3, 2);
        p0 += __shfl_xor_sync(0xffffffffu, p0, 4);
        p1 += __shfl_xor_sync(0xffffffffu, p1, 4);
        p2 += __shfl_xor_sync(0xffffffffu, p2, 4);
        p3 += __shfl_xor_sync(0xffffffffu, p3, 4);
        float e0 = __expf(p0 * 0.25f), e1 = __expf(p1 * 0.25f);
        float e2 = __expf(p2 * 0.25f), e3 = __expf(p3 * 0.25f);
        float2 g0 = __half22float2(va), g1 = __half22float2(vb);
        float2 g2 = __half22float2(vc), g3 = __half22float2(vd);
        acc.x = fmaf(e0, g0.x, acc.x); acc.y = fmaf(e0, g0.y, acc.y);
        acc.x = fmaf(e1, g1.x, acc.x); acc.y = fmaf(e1, g1.y, acc.y);
        acc.x = fmaf(e2, g2.x, acc.x); acc.y = fmaf(e2, g2.y, acc.y);
        acc.x = fmaf(e3, g3.x, acc.x); acc.y = fmaf(e3, g3.y, acc.y);
        den += (e0 + e1) + (e2 + e3);
    }
    for (; i < end; i++) {
        int s = g_csrsrc[i];
        const __half2* r0 = (const __half2*)(g_kvh + (size_t)s * 128);
        float2 kf = __half22float2(r0[lane]);
        float p = fmaf(qv.x, kf.x, qv.y * kf.y);
        p += __shfl_xor_sync(0xffffffffu, p, 1);
        p += __shfl_xor_sync(0xffffffffu, p, 2);
        p += __shfl_xor_sync(0xffffffffu, p, 4);
        float e = __expf(p * 0.25f);
        float2 vf = __half22float2(r0[32 + lane]);
        acc.x = fmaf(e, vf.x, acc.x);
        acc.y = fmaf(e, vf.y, acc.y);
        den += e;
    }

    float inv = (den > 0.f) ? __frcp_rn(den) : 0.f;
    int c0 = lane * 2, c1 = c0 + 1;
    float2 sk = ((const float2*)(g_skip + (size_t)node * 64))[lane];
    float v0 = acc.x * inv + sk.x;
    float v1 = acc.y * inv + sk.y;
    v0 = (v0 - bm[c0]) * rsqrtf(bvv[c0] + EPSV) * bg[c0] + bb[c0];
    v1 = (v1 - bm[c1]) * rsqrtf(bvv[c1] + EPSV) * bg[c1] + bb[c1];
    ((float2*)(g_x + (size_t)node * 64))[lane] = make_float2(fmaxf(v0, 0.f), fmaxf(v1, 0.f));
}

// ================= head GEMM: [N,64] x [64,32] =================
__global__ void k_head(const float* __restrict__ Wh, const float* __restrict__ bh,
                       float* __restrict__ out) {
    __shared__ float xs[8 * 64];
    __shared__ float ws[64 * 32];
    int t = threadIdx.x;
    int node0 = blockIdx.x * 8;
    xs[t]       = g_x[(size_t)node0 * 64 + t];
    xs[t + 256] = g_x[(size_t)node0 * 64 + t + 256];
#pragma unroll
    for (int i = 0; i < 8; i++) ws[t + 256 * i] = Wh[t + 256 * i];
    __syncthreads();
    int ln = t >> 5, col = t & 31;
    float acc = bh[col];
#pragma unroll 4
    for (int kk = 0; kk < 64; kk++)
        acc = fmaf(xs[ln * 64 + kk], ws[kk * 32 + col], acc);
    out[(size_t)(node0 + ln) * 32 + col] = acc;
}

// ================= launch =================
extern "C" void kernel_launch(void* const* d_in, const int* in_sizes, int n_in,
                              void* d_out, int out_size) {
    const float* x    = (const float*)d_in[0];
    const int*   ei   = (const int*)  d_in[1];
    const float* Wq   = (const float*)d_in[2];
    const float* bq   = (const float*)d_in[3];
    const float* Wk   = (const float*)d_in[4];
    const float* bk   = (const float*)d_in[5];
    const float* Wv   = (const float*)d_in[6];
    const float* bv   = (const float*)d_in[7];
    const float* Ws   = (const float*)d_in[8];
    const float* bs   = (const float*)d_in[9];
    const float* bn_g = (const float*)d_in[10];
    const float* bn_b = (const float*)d_in[11];
    const float* bn_m = (const float*)d_in[12];
    const float* bn_v = (const float*)d_in[13];
    const float* Wh   = (const float*)d_in[14];
    const float* bh   = (const float*)d_in[15];
    float* out = (float*)d_out;

    const int NB   = (NN + 255) / 256;
    const int EB   = (EE + 255) / 256;
    const int SBLK = (NN + 1023) / 1024;       // 98
    const int GA   = (NN * 32 + 255) / 256;    // warp per node
    const int GH   = NN / 8;
    const int GR   = (NN + 127) / 128;         // 782

    k_zero_cnt<<<NB, 256>>>();
    k_hist<<<EB, 256>>>(ei);
    k_scan1<<<SBLK, 1024>>>();
    k_scan2<<<1, 128>>>(SBLK);
    k_scan3<<<NB, 256>>>();
    k_scatter<<<EB, 256>>>(ei);

    for (int l = 0; l < 3; l++) {
        size_t wo = (size_t)l * HID * HID;
        size_t bo = (size_t)l * HID;
        const float* xin = (l == 0) ? x : nullptr;
        k_wprep<<<32, 256>>>(Wq + wo, Wk + wo, Wv + wo, Ws + wo);
        k_gemm_mma<<<dim3(GR, 4), 256>>>(xin, bq + bo, bk + bo, bv + bo, bs + bo);
        k_attn<<<GA, 256>>>(bn_g + bo, bn_b + bo, bn_m + bo, bn_v + bo);
    }
    k_head<<<GH, 256>>>(Wh, bh, out);
}

// round 4
// speedup vs baseline: 2.3591x; 1.0393x over previous
#include <cuda_runtime.h>
#include <cuda_fp16.h>
#include <cstdint>

#define NN 100000
#define EE 1600000
#define HID 64
#define OC 32
#define EPSV 1e-5f

// ---------------- scratch (device globals) ----------------
__device__ float  g_q[(size_t)NN * HID];
__device__ float  g_skip[(size_t)NN * HID];
__device__ float  g_x[(size_t)NN * HID];
__device__ __half g_kvh[(size_t)NN * 128];      // per node: k[64] halves then v[64] halves (256 B)
__device__ float4 g_wf[3 * 4 * 8 * 8 * 32];     // per layer, W in mma B-frag order {bhi0,bhi1,blo0,blo1}

__device__ int g_cnt[NN];
__device__ int g_rowstart[NN + 1];
__device__ int g_cursor[NN];
__device__ int g_csrsrc[EE];
__device__ int g_bsum[128];
__device__ int g_boff[128];

// ================= CSR build (once, reused by 3 layers) =================
__global__ void k_zero_cnt() {
    int i = blockIdx.x * blockDim.x + threadIdx.x;
    if (i < NN) g_cnt[i] = 0;
}
__global__ void k_hist(const int* __restrict__ ei) {
    int e = blockIdx.x * blockDim.x + threadIdx.x;
    if (e < EE) atomicAdd(&g_cnt[ei[EE + e]], 1);
}
__global__ void k_scan1() {
    __shared__ int sh[1024];
    int i = blockIdx.x * 1024 + threadIdx.x;
    int v = (i < NN) ? g_cnt[i] : 0;
    sh[threadIdx.x] = v;
    __syncthreads();
    for (int off = 1; off < 1024; off <<= 1) {
        int t = (threadIdx.x >= off) ? sh[threadIdx.x - off] : 0;
        __syncthreads();
        sh[threadIdx.x] += t;
        __syncthreads();
    }
    if (i < NN) g_rowstart[i] = sh[threadIdx.x] - v;
    if (threadIdx.x == 1023) g_bsum[blockIdx.x] = sh[1023];
}
__global__ void k_scan2(int nblk) {
    __shared__ int sh[128];
    int t = threadIdx.x;
    int v = (t < nblk) ? g_bsum[t] : 0;
    sh[t] = v;
    __syncthreads();
    for (int off = 1; off < 128; off <<= 1) {
        int u = (t >= off) ? sh[t - off] : 0;
        __syncthreads();
        sh[t] += u;
        __syncthreads();
    }
    if (t < nblk) g_boff[t] = sh[t] - v;
}
__global__ void k_scan3() {
    int i = blockIdx.x * blockDim.x + threadIdx.x;
    if (i < NN) {
        int rs = g_rowstart[i] + g_boff[i >> 10];
        g_rowstart[i] = rs;
        g_cursor[i] = rs;
    }
    if (i == 0) g_rowstart[NN] = EE;
}
__global__ void k_scatter(const int* __restrict__ ei) {
    int e = blockIdx.x * blockDim.x + threadIdx.x;
    if (e >= EE) return;
    int s = ei[e], d = ei[EE + e];
    int pos = atomicAdd(&g_cursor[d], 1);
    g_csrsrc[pos] = s;
}

// ================= W fragment prep: all 3 layers at once =================
__device__ __forceinline__ uint32_t f2tf32(float f) {
    uint32_t u;
    asm("cvt.rna.tf32.f32 %0, %1;" : "=r"(u) : "f"(f));
    return u;
}
__global__ void k_wprep3(const float* __restrict__ Wq, const float* __restrict__ Wk,
                         const float* __restrict__ Wv, const float* __restrict__ Ws) {
    int t = blockIdx.x * blockDim.x + threadIdx.x;   // 3 * 8192
    if (t >= 3 * 8192) return;
    int layer = t >> 13;
    int r = t & 8191;
    int lane = r & 31;
    int nt   = (r >> 5) & 7;
    int kt   = (r >> 8) & 7;
    int sel  = r >> 11;
    const float* Wb = (sel == 0) ? Wq : (sel == 1) ? Wk : (sel == 2) ? Wv : Ws;
    const float* W = Wb + (size_t)layer * HID * HID;
    int k0 = kt * 8 + (lane & 3);
    int n  = nt * 8 + (lane >> 2);
    float b0 = W[k0 * 64 + n];
    float b1 = W[(k0 + 4) * 64 + n];
    float h0 = __uint_as_float(f2tf32(b0));
    float h1 = __uint_as_float(f2tf32(b1));
    float l0 = __uint_as_float(f2tf32(b0 - h0));
    float l1 = __uint_as_float(f2tf32(b1 - h1));
    g_wf[t] = make_float4(h0, h1, l0, l1);
}

// ================= fused QKVS GEMM: one block = 64 rows, ALL 4 matrices =================
__device__ __forceinline__ void mma_tf32(float* c, uint32_t a0, uint32_t a1,
                                         uint32_t a2, uint32_t a3,
                                         uint32_t b0, uint32_t b1) {
    asm volatile("mma.sync.aligned.m16n8k8.row.col.f32.tf32.tf32.f32 "
                 "{%0,%1,%2,%3}, {%4,%5,%6,%7}, {%8,%9}, {%0,%1,%2,%3};"
                 : "+f"(c[0]), "+f"(c[1]), "+f"(c[2]), "+f"(c[3])
                 : "r"(a0), "r"(a1), "r"(a2), "r"(a3), "r"(b0), "r"(b1));
}

__global__ void __launch_bounds__(256) k_gemm_fused(
        const float* __restrict__ xin, const float4* __restrict__ wf,
        const float* __restrict__ bq, const float* __restrict__ bk,
        const float* __restrict__ bv, const float* __restrict__ bs) {
    __shared__ float xs[64 * 68];
    const float* x = xin ? xin : g_x;
    int row0 = blockIdx.x * 64;
    int t = threadIdx.x;

#pragma unroll
    for (int i = 0; i < 4; i++) {
        int idx = t + 256 * i;          // 1024 float4 = 64 rows x 16
        int r = idx >> 4, c4 = idx & 15;
        float4 val = make_float4(0.f, 0.f, 0.f, 0.f);
        if (row0 + r < NN) val = ((const float4*)(x + (size_t)(row0 + r) * 64))[c4];
        *(float4*)(&xs[r * 68 + c4 * 4]) = val;
    }
    __syncthreads();

    int wid = t >> 5, lane = t & 31;
    int tig = lane & 3, grp = lane >> 2;
    int cloc = wid * 8 + 2 * tig;

    float acc[4][4][4];
    {
        const float* biases[4] = {bq, bk, bv, bs};
#pragma unroll
        for (int sel = 0; sel < 4; sel++) {
            float b0 = biases[sel][cloc], b1 = biases[sel][cloc + 1];
#pragma unroll
            for (int mt = 0; mt < 4; mt++) {
                acc[sel][mt][0] = b0; acc[sel][mt][1] = b1;
                acc[sel][mt][2] = b0; acc[sel][mt][3] = b1;
            }
        }
    }

#pragma unroll
    for (int kt = 0; kt < 8; kt++) {
        uint32_t bh[4][2], bl[4][2];
#pragma unroll
        for (int sel = 0; sel < 4; sel++) {
            float4 bf = wf[((sel * 8 + kt) * 8 + wid) * 32 + lane];
            bh[sel][0] = __float_as_uint(bf.x); bh[sel][1] = __float_as_uint(bf.y);
            bl[sel][0] = __float_as_uint(bf.z); bl[sel][1] = __float_as_uint(bf.w);
        }
        int k = kt * 8 + tig;
#pragma unroll
        for (int mt = 0; mt < 4; mt++) {
            int r = mt * 16 + grp;
            float a0 = xs[r * 68 + k];
            float a1 = xs[(r + 8) * 68 + k];
            float a2 = xs[r * 68 + k + 4];
            float a3 = xs[(r + 8) * 68 + k + 4];
            uint32_t h0 = f2tf32(a0), h1 = f2tf32(a1), h2 = f2tf32(a2), h3 = f2tf32(a3);
            uint32_t l0 = f2tf32(a0 - __uint_as_float(h0));
            uint32_t l1 = f2tf32(a1 - __uint_as_float(h1));
            uint32_t l2 = f2tf32(a2 - __uint_as_float(h2));
            uint32_t l3 = f2tf32(a3 - __uint_as_float(h3));
#pragma unroll
            for (int sel = 0; sel < 4; sel++) {
                mma_tf32(acc[sel][mt], h0, h1, h2, h3, bh[sel][0], bh[sel][1]);
                mma_tf32(acc[sel][mt], h0, h1, h2, h3, bl[sel][0], bl[sel][1]);
                mma_tf32(acc[sel][mt], l0, l1, l2, l3, bh[sel][0], bh[sel][1]);
            }
        }
    }

#pragma unroll
    for (int sel = 0; sel < 4; sel++) {
#pragma unroll
        for (int mt = 0; mt < 4; mt++) {
            int r0g = row0 + mt * 16 + grp;
            int r1g = r0g + 8;
            float* a = acc[sel][mt];
            if (sel == 0) {
                if (r0g < NN) *(float2*)(g_q + (size_t)r0g * 64 + cloc) = make_float2(a[0], a[1]);
                if (r1g < NN) *(float2*)(g_q + (size_t)r1g * 64 + cloc) = make_float2(a[2], a[3]);
            } else if (sel == 3) {
                if (r0g < NN) *(float2*)(g_skip + (size_t)r0g * 64 + cloc) = make_float2(a[0], a[1]);
                if (r1g < NN) *(float2*)(g_skip + (size_t)r1g * 64 + cloc) = make_float2(a[2], a[3]);
            } else {
                int off = (sel == 2) ? 64 : 0;
                if (r0g < NN) *(__half2*)(g_kvh + (size_t)r0g * 128 + off + cloc) = __floats2half2_rn(a[0], a[1]);
                if (r1g < NN) *(__half2*)(g_kvh + (size_t)r1g * 128 + off + cloc) = __floats2half2_rn(a[2], a[3]);
            }
        }
    }
}

// ================= fused attention: warp/node, lane=(edge-group, channel-chunk) =================
// lane = 8*g + j : g in 0..3 = which of 4 concurrent edges, j in 0..7 = channels [8j,8j+8).
// Per quad: each lane does ONE uint4 k-load + ONE uint4 v-load of its edge,
// 8-ch partial dot, 1 shfl (chunk pair -> head dot), exp, 8-ch fma accumulate.
// Accumulators distributed; reduced across groups (shfl xor 8,16) once at the end.
__global__ void k_attn(const float* __restrict__ bg, const float* __restrict__ bb,
                       const float* __restrict__ bm, const float* __restrict__ bvv) {
    int warp = (blockIdx.x * blockDim.x + threadIdx.x) >> 5;
    if (warp >= NN) return;
    int lane = threadIdx.x & 31;
    int g = lane >> 3, j = lane & 7;
    int node = warp;

    const float4* q4 = (const float4*)(g_q + (size_t)node * 64);
    float4 qa = q4[2 * j], qb = q4[2 * j + 1];

    int beg = g_rowstart[node];
    int end = g_rowstart[node + 1];

    float a[8] = {0.f, 0.f, 0.f, 0.f, 0.f, 0.f, 0.f, 0.f};
    float den = 0.f;

    for (int i = beg; i < end; i += 4) {
        int eidx = i + g;
        bool act = eidx < end;
        int s = g_csrsrc[act ? eidx : beg];
        const uint4* kv = (const uint4*)(g_kvh + (size_t)s * 128);
        uint4 kk = kv[j];        // k halves [8j, 8j+8)
        uint4 vv = kv[8 + j];    // v halves [8j, 8j+8)

        float2 k0 = __half22float2(*(__half2*)&kk.x);
        float2 k1 = __half22float2(*(__half2*)&kk.y);
        float2 k2 = __half22float2(*(__half2*)&kk.z);
        float2 k3 = __half22float2(*(__half2*)&kk.w);
        float p = qa.x * k0.x + qa.y * k0.y + qa.z * k1.x + qa.w * k1.y
                + qb.x * k2.x + qb.y * k2.y + qb.z * k3.x + qb.w * k3.y;
        p += __shfl_xor_sync(0xffffffffu, p, 1);     // chunk pair -> full 16-ch head dot
        float ex = act ? __expf(p * 0.25f) : 0.f;    // 1/sqrt(16)

        float2 v0 = __half22float2(*(__half2*)&vv.x);
        float2 v1 = __half22float2(*(__half2*)&vv.y);
        float2 v2 = __half22float2(*(__half2*)&vv.z);
        float2 v3 = __half22float2(*(__half2*)&vv.w);
        a[0] = fmaf(ex, v0.x, a[0]); a[1] = fmaf(ex, v0.y, a[1]);
        a[2] = fmaf(ex, v1.x, a[2]); a[3] = fmaf(ex, v1.y, a[3]);
        a[4] = fmaf(ex, v2.x, a[4]); a[5] = fmaf(ex, v2.y, a[5]);
        a[6] = fmaf(ex, v3.x, a[6]); a[7] = fmaf(ex, v3.y, a[7]);
        den += ex;
    }

    // reduce across the 4 edge groups (lanes xor 8, xor 16)
#pragma unroll
    for (int c = 0; c < 8; c++) {
        a[c] += __shfl_xor_sync(0xffffffffu, a[c], 8);
        a[c] += __shfl_xor_sync(0xffffffffu, a[c], 16);
    }
    den += __shfl_xor_sync(0xffffffffu, den, 8);
    den += __shfl_xor_sync(0xffffffffu, den, 16);

    if (g == 0) {
        float inv = (den > 0.f) ? __frcp_rn(den) : 0.f;
        float4 ska = ((const float4*)(g_skip + (size_t)node * 64))[2 * j];
        float4 skb = ((const float4*)(g_skip + (size_t)node * 64))[2 * j + 1];
        float4 bga = ((const float4*)bg)[2 * j],  bgb = ((const float4*)bg)[2 * j + 1];
        float4 bba = ((const float4*)bb)[2 * j],  bbb = ((const float4*)bb)[2 * j + 1];
        float4 bma = ((const float4*)bm)[2 * j],  bmb = ((const float4*)bm)[2 * j + 1];
        float4 bva = ((const float4*)bvv)[2 * j], bvb = ((const float4*)bvv)[2 * j + 1];
        float o[8];
        o[0] = a[0] * inv + ska.x; o[1] = a[1] * inv + ska.y;
        o[2] = a[2] * inv + ska.z; o[3] = a[3] * inv + ska.w;
        o[4] = a[4] * inv + skb.x; o[5] = a[5] * inv + skb.y;
        o[6] = a[6] * inv + skb.z; o[7] = a[7] * inv + skb.w;
        o[0] = fmaxf((o[0] - bma.x) * rsqrtf(bva.x + EPSV) * bga.x + bba.x, 0.f);
        o[1] = fmaxf((o[1] - bma.y) * rsqrtf(bva.y + EPSV) * bga.y + bba.y, 0.f);
        o[2] = fmaxf((o[2] - bma.z) * rsqrtf(bva.z + EPSV) * bga.z + bba.z, 0.f);
        o[3] = fmaxf((o[3] - bma.w) * rsqrtf(bva.w + EPSV) * bga.w + bba.w, 0.f);
        o[4] = fmaxf((o[4] - bmb.x) * rsqrtf(bvb.x + EPSV) * bgb.x + bbb.x, 0.f);
        o[5] = fmaxf((o[5] - bmb.y) * rsqrtf(bvb.y + EPSV) * bgb.y + bbb.y, 0.f);
        o[6] = fmaxf((o[6] - bmb.z) * rsqrtf(bvb.z + EPSV) * bgb.z + bbb.z, 0.f);
        o[7] = fmaxf((o[7] - bmb.w) * rsqrtf(bvb.w + EPSV) * bgb.w + bbb.w, 0.f);
        float4* xo = (float4*)(g_x + (size_t)node * 64);
        xo[2 * j]     = make_float4(o[0], o[1], o[2], o[3]);
        xo[2 * j + 1] = make_float4(o[4], o[5], o[6], o[7]);
    }
}

// ================= head GEMM: [N,64] x [64,32] =================
__global__ void k_head(const float* __restrict__ Wh, const float* __restrict__ bh,
                       float* __restrict__ out) {
    __shared__ float xs[8 * 64];
    __shared__ float ws[64 * 32];
    int t = threadIdx.x;
    int node0 = blockIdx.x * 8;
    xs[t]       = g_x[(size_t)node0 * 64 + t];
    xs[t + 256] = g_x[(size_t)node0 * 64 + t + 256];
#pragma unroll
    for (int i = 0; i < 8; i++) ws[t + 256 * i] = Wh[t + 256 * i];
    __syncthreads();
    int ln = t >> 5, col = t & 31;
    float acc = bh[col];
#pragma unroll 4
    for (int kk = 0; kk < 64; kk++)
        acc = fmaf(xs[ln * 64 + kk], ws[kk * 32 + col], acc);
    out[(size_t)(node0 + ln) * 32 + col] = acc;
}

// ================= launch =================
extern "C" void kernel_launch(void* const* d_in, const int* in_sizes, int n_in,
                              void* d_out, int out_size) {
    const float* x    = (const float*)d_in[0];
    const int*   ei   = (const int*)  d_in[1];
    const float* Wq   = (const float*)d_in[2];
    const float* bq   = (const float*)d_in[3];
    const float* Wk   = (const float*)d_in[4];
    const float* bk   = (const float*)d_in[5];
    const float* Wv   = (const float*)d_in[6];
    const float* bv   = (const float*)d_in[7];
    const float* Ws   = (const float*)d_in[8];
    const float* bs   = (const float*)d_in[9];
    const float* bn_g = (const float*)d_in[10];
    const float* bn_b = (const float*)d_in[11];
    const float* bn_m = (const float*)d_in[12];
    const float* bn_v = (const float*)d_in[13];
    const float* Wh   = (const float*)d_in[14];
    const float* bh   = (const float*)d_in[15];
    float* out = (float*)d_out;

    const int NB   = (NN + 255) / 256;
    const int EB   = (EE + 255) / 256;
    const int SBLK = (NN + 1023) / 1024;       // 98
    const int GA   = (NN * 32 + 255) / 256;    // warp per node
    const int GH   = NN / 8;
    const int GR   = (NN + 63) / 64;           // 1563

    float4* wf_base;
    cudaGetSymbolAddress((void**)&wf_base, g_wf);

    k_wprep3<<<96, 256>>>(Wq, Wk, Wv, Ws);
    k_zero_cnt<<<NB, 256>>>();
    k_hist<<<EB, 256>>>(ei);
    k_scan1<<<SBLK, 1024>>>();
    k_scan2<<<1, 128>>>(SBLK);
    k_scan3<<<NB, 256>>>();
    k_scatter<<<EB, 256>>>(ei);

    for (int l = 0; l < 3; l++) {
        size_t bo = (size_t)l * HID;
        const float* xin = (l == 0) ? x : nullptr;
        k_gemm_fused<<<GR, 256>>>(xin, wf_base + (size_t)l * 8192,
                                  bq + bo, bk + bo, bv + bo, bs + bo);
        k_attn<<<GA, 256>>>(bn_g + bo, bn_b + bo, bn_m + bo, bn_v + bo);
    }
    k_head<<<GH, 256>>>(Wh, bh, out);
}

// round 5
// speedup vs baseline: 2.9541x; 1.2522x over previous
#include <cuda_runtime.h>
#include <cuda_fp16.h>
#include <cuda_bf16.h>
#include <cstdint>

#define NN 100000
#define EE 1600000
#define HID 64
#define OC 32
#define EPSV 1e-5f

// ---------------- scratch (device globals) ----------------
__device__ float  g_q[(size_t)NN * HID];
__device__ float  g_skip[(size_t)NN * HID];
__device__ float  g_x[(size_t)NN * HID];
__device__ __half g_kvh[(size_t)NN * 128];   // per node: k[64] halves then v[64] halves (256 B)
__device__ uint4  g_wf[3 * 4096];            // per layer: 4 sel x 4 kt x 8 nt x 32 lanes, {bh0,bh1,bl0,bl1}

__device__ int g_cnt[NN];
__device__ int g_rowstart[NN + 1];
__device__ int g_cursor[NN];
__device__ int g_csrsrc[EE];
__device__ int g_bsum[128];
__device__ int g_boff[128];

// ================= CSR build (once, reused by 3 layers) =================
__global__ void k_zero_cnt() {
    int i = blockIdx.x * blockDim.x + threadIdx.x;
    if (i < NN) g_cnt[i] = 0;
}
__global__ void k_hist(const int* __restrict__ ei) {
    int e = blockIdx.x * blockDim.x + threadIdx.x;
    if (e < EE) atomicAdd(&g_cnt[ei[EE + e]], 1);
}
__global__ void k_scan1() {
    __shared__ int sh[1024];
    int i = blockIdx.x * 1024 + threadIdx.x;
    int v = (i < NN) ? g_cnt[i] : 0;
    sh[threadIdx.x] = v;
    __syncthreads();
    for (int off = 1; off < 1024; off <<= 1) {
        int t = (threadIdx.x >= off) ? sh[threadIdx.x - off] : 0;
        __syncthreads();
        sh[threadIdx.x] += t;
        __syncthreads();
    }
    if (i < NN) g_rowstart[i] = sh[threadIdx.x] - v;
    if (threadIdx.x == 1023) g_bsum[blockIdx.x] = sh[1023];
}
__global__ void k_scan2(int nblk) {
    __shared__ int sh[128];
    int t = threadIdx.x;
    int v = (t < nblk) ? g_bsum[t] : 0;
    sh[t] = v;
    __syncthreads();
    for (int off = 1; off < 128; off <<= 1) {
        int u = (t >= off) ? sh[t - off] : 0;
        __syncthreads();
        sh[t] += u;
        __syncthreads();
    }
    if (t < nblk) g_boff[t] = sh[t] - v;
}
__global__ void k_scan3() {
    int i = blockIdx.x * blockDim.x + threadIdx.x;
    if (i < NN) {
        int rs = g_rowstart[i] + g_boff[i >> 10];
        g_rowstart[i] = rs;
        g_cursor[i] = rs;
    }
    if (i == 0) g_rowstart[NN] = EE;
}
__global__ void k_scatter(const int* __restrict__ ei) {
    int e = blockIdx.x * blockDim.x + threadIdx.x;
    if (e >= EE) return;
    int s = ei[e], d = ei[EE + e];
    int pos = atomicAdd(&g_cursor[d], 1);
    g_csrsrc[pos] = s;
}

// ================= W fragment prep (bf16 hi/lo, all 3 layers) =================
// mma.m16n8k16 row.col B frag: b0={B[2t][n],B[2t+1][n]}, b1={B[2t+8][n],B[2t+9][n]}, n=grp, t=tig
__global__ void k_wprep3(const float* __restrict__ Wq, const float* __restrict__ Wk,
                         const float* __restrict__ Wv, const float* __restrict__ Ws) {
    int t = blockIdx.x * blockDim.x + threadIdx.x;   // 3 * 4096
    if (t >= 3 * 4096) return;
    int lane  = t & 31;
    int nt    = (t >> 5) & 7;
    int kt    = (t >> 8) & 3;
    int sel   = (t >> 10) & 3;
    int layer = t >> 12;
    const float* Wb = (sel == 0) ? Wq : (sel == 1) ? Wk : (sel == 2) ? Wv : Ws;
    const float* W = Wb + (size_t)layer * HID * HID;
    int grp = lane >> 2, tig = lane & 3;
    int n  = nt * 8 + grp;
    int k0 = kt * 16 + tig * 2;

    float b00 = W[k0 * 64 + n],       b01 = W[(k0 + 1) * 64 + n];
    float b10 = W[(k0 + 8) * 64 + n], b11 = W[(k0 + 9) * 64 + n];

    __nv_bfloat162 h0 = __floats2bfloat162_rn(b00, b01);
    __nv_bfloat162 h1 = __floats2bfloat162_rn(b10, b11);
    __nv_bfloat162 l0 = __floats2bfloat162_rn(b00 - __bfloat162float(h0.x),
                                              b01 - __bfloat162float(h0.y));
    __nv_bfloat162 l1 = __floats2bfloat162_rn(b10 - __bfloat162float(h1.x),
                                              b11 - __bfloat162float(h1.y));
    uint4 o;
    o.x = *(uint32_t*)&h0; o.y = *(uint32_t*)&h1;
    o.z = *(uint32_t*)&l0; o.w = *(uint32_t*)&l1;
    g_wf[t] = o;
}

// ================= fused QKVS GEMM: bf16 hi/lo 3-pass, one block = 64 rows, all 4 matrices =================
__device__ __forceinline__ void mma_bf16(float* c, uint32_t a0, uint32_t a1,
                                         uint32_t a2, uint32_t a3,
                                         uint32_t b0, uint32_t b1) {
    asm volatile("mma.sync.aligned.m16n8k16.row.col.f32.bf16.bf16.f32 "
                 "{%0,%1,%2,%3}, {%4,%5,%6,%7}, {%8,%9}, {%0,%1,%2,%3};"
                 : "+f"(c[0]), "+f"(c[1]), "+f"(c[2]), "+f"(c[3])
                 : "r"(a0), "r"(a1), "r"(a2), "r"(a3), "r"(b0), "r"(b1));
}

__device__ __forceinline__ void split_pair(float a, float b, uint32_t& hi, uint32_t& lo) {
    __nv_bfloat162 h = __floats2bfloat162_rn(a, b);
    __nv_bfloat162 l = __floats2bfloat162_rn(a - __bfloat162float(h.x),
                                             b - __bfloat162float(h.y));
    hi = *(uint32_t*)&h;
    lo = *(uint32_t*)&l;
}

__global__ void __launch_bounds__(256) k_gemm_fused(
        const float* __restrict__ xin, const uint4* __restrict__ wf,
        const float* __restrict__ bq, const float* __restrict__ bk,
        const float* __restrict__ bv, const float* __restrict__ bs) {
    __shared__ float xs[64 * 68];
    const float* x = xin ? xin : g_x;
    int row0 = blockIdx.x * 64;
    int t = threadIdx.x;

#pragma unroll
    for (int i = 0; i < 4; i++) {
        int idx = t + 256 * i;
        int r = idx >> 4, c4 = idx & 15;
        float4 val = make_float4(0.f, 0.f, 0.f, 0.f);
        if (row0 + r < NN) val = ((const float4*)(x + (size_t)(row0 + r) * 64))[c4];
        *(float4*)(&xs[r * 68 + c4 * 4]) = val;
    }
    __syncthreads();

    int wid = t >> 5, lane = t & 31;
    int tig = lane & 3, grp = lane >> 2;
    int cloc = wid * 8 + 2 * tig;

    float acc[4][4][4];
    {
        const float* biases[4] = {bq, bk, bv, bs};
#pragma unroll
        for (int sel = 0; sel < 4; sel++) {
            float b0 = biases[sel][cloc], b1 = biases[sel][cloc + 1];
#pragma unroll
            for (int mt = 0; mt < 4; mt++) {
                acc[sel][mt][0] = b0; acc[sel][mt][1] = b1;
                acc[sel][mt][2] = b0; acc[sel][mt][3] = b1;
            }
        }
    }

#pragma unroll
    for (int kt = 0; kt < 4; kt++) {
        uint4 bf[4];
#pragma unroll
        for (int sel = 0; sel < 4; sel++)
            bf[sel] = wf[((sel * 4 + kt) * 8 + wid) * 32 + lane];
        int k = kt * 16 + tig * 2;
#pragma unroll
        for (int mt = 0; mt < 4; mt++) {
            int r = mt * 16 + grp;
            float a00 = xs[r * 68 + k],           a01 = xs[r * 68 + k + 1];
            float a10 = xs[(r + 8) * 68 + k],     a11 = xs[(r + 8) * 68 + k + 1];
            float a20 = xs[r * 68 + k + 8],       a21 = xs[r * 68 + k + 9];
            float a30 = xs[(r + 8) * 68 + k + 8], a31 = xs[(r + 8) * 68 + k + 9];
            uint32_t h0, l0, h1, l1, h2, l2, h3, l3;
            split_pair(a00, a01, h0, l0);
            split_pair(a10, a11, h1, l1);
            split_pair(a20, a21, h2, l2);
            split_pair(a30, a31, h3, l3);
#pragma unroll
            for (int sel = 0; sel < 4; sel++) {
                mma_bf16(acc[sel][mt], h0, h1, h2, h3, bf[sel].x, bf[sel].y);  // hi*hi
                mma_bf16(acc[sel][mt], h0, h1, h2, h3, bf[sel].z, bf[sel].w);  // hi*lo
                mma_bf16(acc[sel][mt], l0, l1, l2, l3, bf[sel].x, bf[sel].y);  // lo*hi
            }
        }
    }

#pragma unroll
    for (int sel = 0; sel < 4; sel++) {
#pragma unroll
        for (int mt = 0; mt < 4; mt++) {
            int r0g = row0 + mt * 16 + grp;
            int r1g = r0g + 8;
            float* a = acc[sel][mt];
            if (sel == 0) {
                if (r0g < NN) *(float2*)(g_q + (size_t)r0g * 64 + cloc) = make_float2(a[0], a[1]);
                if (r1g < NN) *(float2*)(g_q + (size_t)r1g * 64 + cloc) = make_float2(a[2], a[3]);
            } else if (sel == 3) {
                if (r0g < NN) *(float2*)(g_skip + (size_t)r0g * 64 + cloc) = make_float2(a[0], a[1]);
                if (r1g < NN) *(float2*)(g_skip + (size_t)r1g * 64 + cloc) = make_float2(a[2], a[3]);
            } else {
                int off = (sel == 2) ? 64 : 0;
                if (r0g < NN) *(__half2*)(g_kvh + (size_t)r0g * 128 + off + cloc) = __floats2half2_rn(a[0], a[1]);
                if (r1g < NN) *(__half2*)(g_kvh + (size_t)r1g * 128 + off + cloc) = __floats2half2_rn(a[2], a[3]);
            }
        }
    }
}

// ================= fused attention: warp/node, 8 edges in flight =================
__device__ __forceinline__ float dot8(const float4& qa, const float4& qb, const uint4& kk) {
    float2 k0 = __half22float2(*(__half2*)&kk.x);
    float2 k1 = __half22float2(*(__half2*)&kk.y);
    float2 k2 = __half22float2(*(__half2*)&kk.z);
    float2 k3 = __half22float2(*(__half2*)&kk.w);
    return qa.x * k0.x + qa.y * k0.y + qa.z * k1.x + qa.w * k1.y
         + qb.x * k2.x + qb.y * k2.y + qb.z * k3.x + qb.w * k3.y;
}
__device__ __forceinline__ void acc8(float* a, float ex, const uint4& vv) {
    float2 v0 = __half22float2(*(__half2*)&vv.x);
    float2 v1 = __half22float2(*(__half2*)&vv.y);
    float2 v2 = __half22float2(*(__half2*)&vv.z);
    float2 v3 = __half22float2(*(__half2*)&vv.w);
    a[0] = fmaf(ex, v0.x, a[0]); a[1] = fmaf(ex, v0.y, a[1]);
    a[2] = fmaf(ex, v1.x, a[2]); a[3] = fmaf(ex, v1.y, a[3]);
    a[4] = fmaf(ex, v2.x, a[4]); a[5] = fmaf(ex, v2.y, a[5]);
    a[6] = fmaf(ex, v3.x, a[6]); a[7] = fmaf(ex, v3.y, a[7]);
}

__global__ void k_attn(const float* __restrict__ bg, const float* __restrict__ bb,
                       const float* __restrict__ bm, const float* __restrict__ bvv) {
    int warp = (blockIdx.x * blockDim.x + threadIdx.x) >> 5;
    if (warp >= NN) return;
    int lane = threadIdx.x & 31;
    int g = lane >> 3, j = lane & 7;
    int node = warp;

    const float4* q4 = (const float4*)(g_q + (size_t)node * 64);
    float4 qa = q4[2 * j], qb = q4[2 * j + 1];

    int beg = g_rowstart[node];
    int end = g_rowstart[node + 1];

    float a[8] = {0.f, 0.f, 0.f, 0.f, 0.f, 0.f, 0.f, 0.f};
    float den = 0.f;
    int i = beg;

    // main loop: 8 edges in flight (two quad batches, independent loads)
    for (; i + 8 <= end; i += 8) {
        int sA = g_csrsrc[i + g];
        int sB = g_csrsrc[i + 4 + g];
        const uint4* kvA = (const uint4*)(g_kvh + (size_t)sA * 128);
        const uint4* kvB = (const uint4*)(g_kvh + (size_t)sB * 128);
        uint4 kA = kvA[j];
        uint4 kB = kvB[j];
        uint4 vA = kvA[8 + j];
        uint4 vB = kvB[8 + j];

        float pA = dot8(qa, qb, kA);
        float pB = dot8(qa, qb, kB);
        pA += __shfl_xor_sync(0xffffffffu, pA, 1);
        pB += __shfl_xor_sync(0xffffffffu, pB, 1);
        float eA = __expf(pA * 0.25f);
        float eB = __expf(pB * 0.25f);
        acc8(a, eA, vA);
        acc8(a, eB, vB);
        den += eA + eB;
    }
    // remainder: masked quads
    for (; i < end; i += 4) {
        int eidx = i + g;
        bool act = eidx < end;
        int s = g_csrsrc[act ? eidx : beg];
        const uint4* kv = (const uint4*)(g_kvh + (size_t)s * 128);
        uint4 kk = kv[j];
        uint4 vv = kv[8 + j];
        float p = dot8(qa, qb, kk);
        p += __shfl_xor_sync(0xffffffffu, p, 1);
        float ex = act ? __expf(p * 0.25f) : 0.f;
        acc8(a, ex, vv);
        den += ex;
    }

    // reduce across the 4 edge groups
#pragma unroll
    for (int c = 0; c < 8; c++) {
        a[c] += __shfl_xor_sync(0xffffffffu, a[c], 8);
        a[c] += __shfl_xor_sync(0xffffffffu, a[c], 16);
    }
    den += __shfl_xor_sync(0xffffffffu, den, 8);
    den += __shfl_xor_sync(0xffffffffu, den, 16);

    if (g == 0) {
        float inv = (den > 0.f) ? __frcp_rn(den) : 0.f;
        float4 ska = ((const float4*)(g_skip + (size_t)node * 64))[2 * j];
        float4 skb = ((const float4*)(g_skip + (size_t)node * 64))[2 * j + 1];
        float4 bga = ((const float4*)bg)[2 * j],  bgb = ((const float4*)bg)[2 * j + 1];
        float4 bba = ((const float4*)bb)[2 * j],  bbb = ((const float4*)bb)[2 * j + 1];
        float4 bma = ((const float4*)bm)[2 * j],  bmb = ((const float4*)bm)[2 * j + 1];
        float4 bva = ((const float4*)bvv)[2 * j], bvb = ((const float4*)bvv)[2 * j + 1];
        float o[8];
        o[0] = a[0] * inv + ska.x; o[1] = a[1] * inv + ska.y;
        o[2] = a[2] * inv + ska.z; o[3] = a[3] * inv + ska.w;
        o[4] = a[4] * inv + skb.x; o[5] = a[5] * inv + skb.y;
        o[6] = a[6] * inv + skb.z; o[7] = a[7] * inv + skb.w;
        o[0] = fmaxf((o[0] - bma.x) * rsqrtf(bva.x + EPSV) * bga.x + bba.x, 0.f);
        o[1] = fmaxf((o[1] - bma.y) * rsqrtf(bva.y + EPSV) * bga.y + bba.y, 0.f);
        o[2] = fmaxf((o[2] - bma.z) * rsqrtf(bva.z + EPSV) * bga.z + bba.z, 0.f);
        o[3] = fmaxf((o[3] - bma.w) * rsqrtf(bva.w + EPSV) * bga.w + bba.w, 0.f);
        o[4] = fmaxf((o[4] - bmb.x) * rsqrtf(bvb.x + EPSV) * bgb.x + bbb.x, 0.f);
        o[5] = fmaxf((o[5] - bmb.y) * rsqrtf(bvb.y + EPSV) * bgb.y + bbb.y, 0.f);
        o[6] = fmaxf((o[6] - bmb.z) * rsqrtf(bvb.z + EPSV) * bgb.z + bbb.z, 0.f);
        o[7] = fmaxf((o[7] - bmb.w) * rsqrtf(bvb.w + EPSV) * bgb.w + bbb.w, 0.f);
        float4* xo = (float4*)(g_x + (size_t)node * 64);
        xo[2 * j]     = make_float4(o[0], o[1], o[2], o[3]);
        xo[2 * j + 1] = make_float4(o[4], o[5], o[6], o[7]);
    }
}

// ================= head GEMM: 32 nodes/block, [N,64] x [64,32] =================
__global__ void k_head(const float* __restrict__ Wh, const float* __restrict__ bh,
                       float* __restrict__ out) {
    __shared__ float xs[32 * 64];
    __shared__ float ws[64 * 32];
    int t = threadIdx.x;
    int node0 = blockIdx.x * 32;
    const float4* xsrc = (const float4*)(g_x + (size_t)node0 * 64);
    ((float4*)xs)[t]       = xsrc[t];
    ((float4*)xs)[t + 256] = xsrc[t + 256];
    ((float4*)ws)[t]       = ((const float4*)Wh)[t];
    ((float4*)ws)[t + 256] = ((const float4*)Wh)[t + 256];
    __syncthreads();
    int col = t & 31, nr = t >> 5;
    float a0, a1, a2, a3;
    a0 = a1 = a2 = a3 = bh[col];
#pragma unroll 8
    for (int kk = 0; kk < 64; kk++) {
        float w = ws[kk * 32 + col];
        a0 = fmaf(xs[nr * 64 + kk],        w, a0);
        a1 = fmaf(xs[(nr + 8) * 64 + kk],  w, a1);
        a2 = fmaf(xs[(nr + 16) * 64 + kk], w, a2);
        a3 = fmaf(xs[(nr + 24) * 64 + kk], w, a3);
    }
    out[(size_t)(node0 + nr) * 32 + col]        = a0;
    out[(size_t)(node0 + nr + 8) * 32 + col]    = a1;
    out[(size_t)(node0 + nr + 16) * 32 + col]   = a2;
    out[(size_t)(node0 + nr + 24) * 32 + col]   = a3;
}

// ================= launch =================
extern "C" void kernel_launch(void* const* d_in, const int* in_sizes, int n_in,
                              void* d_out, int out_size) {
    const float* x    = (const float*)d_in[0];
    const int*   ei   = (const int*)  d_in[1];
    const float* Wq   = (const float*)d_in[2];
    const float* bq   = (const float*)d_in[3];
    const float* Wk   = (const float*)d_in[4];
    const float* bk   = (const float*)d_in[5];
    const float* Wv   = (const float*)d_in[6];
    const float* bv   = (const float*)d_in[7];
    const float* Ws   = (const float*)d_in[8];
    const float* bs   = (const float*)d_in[9];
    const float* bn_g = (const float*)d_in[10];
    const float* bn_b = (const float*)d_in[11];
    const float* bn_m = (const float*)d_in[12];
    const float* bn_v = (const float*)d_in[13];
    const float* Wh   = (const float*)d_in[14];
    const float* bh   = (const float*)d_in[15];
    float* out = (float*)d_out;

    const int NB   = (NN + 255) / 256;
    const int EB   = (EE + 255) / 256;
    const int SBLK = (NN + 1023) / 1024;       // 98
    const int GA   = (NN * 32 + 255) / 256;    // warp per node
    const int GH   = NN / 32;                  // 3125
    const int GR   = (NN + 63) / 64;           // 1563

    uint4* wf_base;
    cudaGetSymbolAddress((void**)&wf_base, g_wf);

    k_wprep3<<<48, 256>>>(Wq, Wk, Wv, Ws);
    k_zero_cnt<<<NB, 256>>>();
    k_hist<<<EB, 256>>>(ei);
    k_scan1<<<SBLK, 1024>>>();
    k_scan2<<<1, 128>>>(SBLK);
    k_scan3<<<NB, 256>>>();
    k_scatter<<<EB, 256>>>(ei);

    for (int l = 0; l < 3; l++) {
        size_t bo = (size_t)l * HID;
        const float* xin = (l == 0) ? x : nullptr;
        k_gemm_fused<<<GR, 256>>>(xin, wf_base + (size_t)l * 4096,
                                  bq + bo, bk + bo, bv + bo, bs + bo);
        k_attn<<<GA, 256>>>(bn_g + bo, bn_b + bo, bn_m + bo, bn_v + bo);
    }
    k_head<<<GH, 256>>>(Wh, bh, out);
}